// round 1
// baseline (speedup 1.0000x reference)
#include <cuda_runtime.h>
#include <cuda_bf16.h>
#include <math.h>

// Problem dims
#define TT   512
#define BB   128
#define II   512
#define HH   512
#define G4   2048          // 4*H
#define NBLK 128           // persistent blocks for recurrence (<=148 SMs, all co-resident)

// Scratch (allocation-free rule: __device__ globals)
__device__ float    g_xg[(size_t)TT * BB * G4];   // precomputed x@W_ih^T + bias, [T][B][4H] (512 MB)
__device__ float    g_c[BB * HH];                 // cell state
__device__ unsigned g_sync[2];                    // [0] = arrive counter

// ---------------------------------------------------------------------------
// init: zero cell state + barrier counters (runs every launch -> deterministic)
// ---------------------------------------------------------------------------
__global__ void init_state() {
    int i = blockIdx.x * blockDim.x + threadIdx.x;
    if (i < BB * HH) g_c[i] = 0.0f;
    if (i < 2)       g_sync[i] = 0u;
}

// ---------------------------------------------------------------------------
// Precompute: C[m][n] = dot(X[m,:], W[n,:]) + b1[n] + b2[n]
// M = T*B = 65536, N = 2048, K = 512.  Classic 128x128x8 SGEMM, 8x8/thread.
// ---------------------------------------------------------------------------
__global__ void __launch_bounds__(256) sgemm_ih(const float* __restrict__ X,
                                                const float* __restrict__ W,
                                                const float* __restrict__ b1,
                                                const float* __restrict__ b2)
{
    __shared__ float As[8][128];
    __shared__ float Bs[8][128];

    const int t  = threadIdx.x;
    const int m0 = blockIdx.y * 128;
    const int n0 = blockIdx.x * 128;

    const int lrow = t >> 1;          // 0..127
    const int lk   = (t & 1) * 4;     // 0 or 4
    const float* Xp = X + (size_t)(m0 + lrow) * II + lk;
    const float* Wp = W + (size_t)(n0 + lrow) * II + lk;

    const int tx = t & 15;            // n sub-tile
    const int ty = t >> 4;            // m sub-tile

    float acc[8][8];
#pragma unroll
    for (int i = 0; i < 8; ++i)
#pragma unroll
        for (int j = 0; j < 8; ++j) acc[i][j] = 0.0f;

    for (int k0 = 0; k0 < II; k0 += 8) {
        float4 xa = *(const float4*)(Xp + k0);
        float4 wa = *(const float4*)(Wp + k0);
        __syncthreads();
        As[lk + 0][lrow] = xa.x; As[lk + 1][lrow] = xa.y;
        As[lk + 2][lrow] = xa.z; As[lk + 3][lrow] = xa.w;
        Bs[lk + 0][lrow] = wa.x; Bs[lk + 1][lrow] = wa.y;
        Bs[lk + 2][lrow] = wa.z; Bs[lk + 3][lrow] = wa.w;
        __syncthreads();
#pragma unroll
        for (int k = 0; k < 8; ++k) {
            float a[8], b[8];
            *(float4*)(a)     = *(const float4*)(&As[k][ty * 8]);
            *(float4*)(a + 4) = *(const float4*)(&As[k][ty * 8 + 4]);
            *(float4*)(b)     = *(const float4*)(&Bs[k][tx * 8]);
            *(float4*)(b + 4) = *(const float4*)(&Bs[k][tx * 8 + 4]);
#pragma unroll
            for (int i = 0; i < 8; ++i)
#pragma unroll
                for (int j = 0; j < 8; ++j) acc[i][j] += a[i] * b[j];
        }
    }

    float bj[8];
#pragma unroll
    for (int j = 0; j < 8; ++j) {
        int n = n0 + tx * 8 + j;
        bj[j] = b1[n] + b2[n];
    }
#pragma unroll
    for (int i = 0; i < 8; ++i) {
        int m = m0 + ty * 8 + i;
        float* Cp = g_xg + (size_t)m * G4 + n0 + tx * 8;
        float4 v0 = make_float4(acc[i][0] + bj[0], acc[i][1] + bj[1],
                                acc[i][2] + bj[2], acc[i][3] + bj[3]);
        float4 v1 = make_float4(acc[i][4] + bj[4], acc[i][5] + bj[5],
                                acc[i][6] + bj[6], acc[i][7] + bj[7]);
        *(float4*)(Cp)     = v0;
        *(float4*)(Cp + 4) = v1;
    }
}

// ---------------------------------------------------------------------------
// Persistent recurrent kernel. 128 blocks x 256 threads (8 warps).
// Block g owns h-columns [4g, 4g+4) -> 16 gate rows {q*512 + 4g + ci}.
// Per step: gates_tile[128 x 16] = h_prev @ Whh_slice^T  (warp-split-K, K=64/warp)
// then fused LSTM elementwise, h written straight into d_out (outputs == h seq).
// Grid barrier (atomic counter) between steps.
// Shared: Wt [512][16] (32KB, loaded once) + hs 8 warps x [16][128] (64KB),
// hs reused as per-warp partial-sum buffer (col-major [16][128]) for reduction.
// ---------------------------------------------------------------------------
__global__ void __launch_bounds__(256, 1) lstm_rec(const float* __restrict__ Whh,
                                                   float* __restrict__ out,
                                                   int tail)
{
    extern __shared__ float sm[];
    float* Wt = sm;                // [512][16]
    float* hs = sm + 512 * 16;     // [8][2048]

    const int tid  = threadIdx.x;
    const int w    = tid >> 5;
    const int lane = tid & 31;
    const int hc0  = blockIdx.x * 4;

    // Load W_hh slice transposed: Wt[k][j] = Whh[n_j][k], n_j = (j>>2)*512 + hc0 + (j&3)
    for (int idx = tid; idx < 16 * 512; idx += 256) {
        int j = idx >> 9;
        int k = idx & 511;
        int n = (j >> 2) * 512 + hc0 + (j & 3);
        Wt[k * 16 + j] = Whh[(size_t)n * HH + k];
    }
    __syncthreads();

    const int rbase = lane & 15;          // interleaved rows: b = rbase + 16*rr
    const int cb    = (lane >> 4) * 8;    // col base (0 or 8)
    float* myhs = hs + w * 2048;
    const int kwarp = w * 64;

    for (int t = 0; t < TT; ++t) {
        if (t > 0) {
            float acc[8][8];
#pragma unroll
            for (int rr = 0; rr < 8; ++rr)
#pragma unroll
                for (int cj = 0; cj < 8; ++cj) acc[rr][cj] = 0.0f;

            const float* hp = out + (size_t)(t - 1) * BB * HH;

            // prefetch phase 0 (16 k x 128 b chunk for this warp)
            float4 buf[16];
#pragma unroll
            for (int i = 0; i < 16; ++i) {
                int flat = i * 32 + lane;
                int b = flat >> 2, kq = (flat & 3) * 4;
                buf[i] = *(const float4*)(hp + (size_t)b * HH + kwarp + kq);
            }

            for (int p = 0; p < 4; ++p) {
                // store current chunk transposed: hs[kk][b]
#pragma unroll
                for (int i = 0; i < 16; ++i) {
                    int flat = i * 32 + lane;
                    int b = flat >> 2, kq = (flat & 3) * 4;
                    myhs[(kq + 0) * 128 + b] = buf[i].x;
                    myhs[(kq + 1) * 128 + b] = buf[i].y;
                    myhs[(kq + 2) * 128 + b] = buf[i].z;
                    myhs[(kq + 3) * 128 + b] = buf[i].w;
                }
                __syncwarp();
                // prefetch next chunk while computing this one
                if (p < 3) {
#pragma unroll
                    for (int i = 0; i < 16; ++i) {
                        int flat = i * 32 + lane;
                        int b = flat >> 2, kq = (flat & 3) * 4;
                        buf[i] = *(const float4*)(hp + (size_t)b * HH + kwarp + (p + 1) * 16 + kq);
                    }
                }
#pragma unroll
                for (int kk = 0; kk < 16; ++kk) {
                    float bv[8];
                    const float* wrow = &Wt[(kwarp + p * 16 + kk) * 16 + cb];
                    *(float4*)(bv)     = *(const float4*)(wrow);
                    *(float4*)(bv + 4) = *(const float4*)(wrow + 4);
                    float av[8];
#pragma unroll
                    for (int rr = 0; rr < 8; ++rr)
                        av[rr] = myhs[kk * 128 + rbase + 16 * rr];
#pragma unroll
                    for (int rr = 0; rr < 8; ++rr)
#pragma unroll
                        for (int cj = 0; cj < 8; ++cj)
                            acc[rr][cj] += av[rr] * bv[cj];
                }
                __syncwarp();
            }

            // dump partials, col-major: myhs[col*128 + row]  (2-way conflict max)
#pragma unroll
            for (int rr = 0; rr < 8; ++rr)
#pragma unroll
                for (int cj = 0; cj < 8; ++cj)
                    myhs[(cb + cj) * 128 + rbase + 16 * rr] = acc[rr][cj];
        }
        __syncthreads();

        // Fused reduction + LSTM elementwise. 512 (b,ci) pairs, 2 per thread.
        const float* xgt = g_xg + (size_t)t * BB * G4;
#pragma unroll
        for (int pi = 0; pi < 2; ++pi) {
            int p  = tid + pi * 256;      // 0..511
            int ci = p >> 7;              // 0..3
            int b  = p & 127;
            float gate[4];
#pragma unroll
            for (int q = 0; q < 4; ++q) {
                int col = q * 4 + ci;
                float s = 0.0f;
                if (t > 0) {
#pragma unroll
                    for (int ww = 0; ww < 8; ++ww)
                        s += hs[ww * 2048 + col * 128 + b];
                }
                int n = q * 512 + hc0 + ci;
                gate[q] = s + xgt[(size_t)b * G4 + n];
            }
            float ig = 1.0f / (1.0f + __expf(-gate[0]));
            float fg = 1.0f / (1.0f + __expf(-gate[1]));
            float gg = tanhf(gate[2]);
            float og = 1.0f / (1.0f + __expf(-gate[3]));
            int cidx = b * HH + hc0 + ci;
            float c  = g_c[cidx];               // zeroed by init for t==0
            float cn = fg * c + ig * gg;
            g_c[cidx] = cn;
            out[(size_t)t * BB * HH + cidx] = og * tanhf(cn);
        }

        // grid barrier between steps
        __syncthreads();
        if (tid == 0) {
            __threadfence();
            atomicAdd(&g_sync[0], 1u);
            unsigned target = (unsigned)(t + 1) * NBLK;
            while (*(volatile unsigned*)&g_sync[0] < target) { }
            __threadfence();
        }
        __syncthreads();
    }

    // tail: hT (copy of last h) and cT, if the output buffer includes them
    if (tail) {
        for (int p = tid; p < 512; p += 256) {
            int ci = p >> 7, b = p & 127;
            int cidx = b * HH + hc0 + ci;
            out[(size_t)TT * BB * HH + cidx]           = out[(size_t)(TT - 1) * BB * HH + cidx];
            out[(size_t)TT * BB * HH + BB * HH + cidx] = g_c[cidx];
        }
    }
}

// ---------------------------------------------------------------------------
extern "C" void kernel_launch(void* const* d_in, const int* in_sizes, int n_in,
                              void* d_out, int out_size)
{
    const float* input = (const float*)d_in[0];
    /* d_in[1] = time, unused by the base cell */
    const float* W_ih  = (const float*)d_in[2];
    const float* W_hh  = (const float*)d_in[3];
    const float* b_ih  = (const float*)d_in[4];
    const float* b_hh  = (const float*)d_in[5];
    float* out = (float*)d_out;

    const long long TBH = (long long)TT * BB * HH;
    int tail = (out_size >= TBH + 2LL * BB * HH) ? 1 : 0;

    init_state<<<256, 256>>>();
    sgemm_ih<<<dim3(G4 / 128, (TT * BB) / 128), 256>>>(input, W_ih, b_ih, b_hh);

    cudaFuncSetAttribute(lstm_rec, cudaFuncAttributeMaxDynamicSharedMemorySize, 98304);
    lstm_rec<<<NBLK, 256, 98304>>>(W_hh, out, tail);
}

// round 2
// speedup vs baseline: 1.7559x; 1.7559x over previous
#include <cuda_runtime.h>
#include <cuda_bf16.h>
#include <math.h>
#include <stdint.h>

// Problem dims
#define TT   512
#define BB   128
#define II   512
#define HH   512
#define G4   2048
#define NBLK 128
#define TBH  ((size_t)TT * BB * HH)

// ---------------------------------------------------------------------------
// Device scratch (allocation-free rule)
// ---------------------------------------------------------------------------
__device__ __nv_bfloat16 g_Xhi[(size_t)TT * BB * II];   // 64MB
__device__ __nv_bfloat16 g_Xlo[(size_t)TT * BB * II];   // 64MB
__device__ __nv_bfloat16 g_Whi[G4 * II];                // 2MB
__device__ __nv_bfloat16 g_Wlo[G4 * II];                // 2MB
__device__ float         g_bias[G4];
__device__ float         g_xg[(size_t)TT * BB * G4];    // 512MB
__device__ uint32_t      g_hpk[2][BB * HH];             // packed {hi,lo} bf16 of h, double-buffered
__device__ unsigned      g_sync;

// ---------------------------------------------------------------------------
// Helpers
// ---------------------------------------------------------------------------
__device__ __forceinline__ void split2(float x, uint32_t& h, uint32_t& l) {
    __nv_bfloat16 hb = __float2bfloat16_rn(x);
    float r = x - __bfloat162float(hb);
    __nv_bfloat16 lb = __float2bfloat16_rn(r);
    h = (uint32_t)__bfloat16_as_ushort(hb);
    l = (uint32_t)__bfloat16_as_ushort(lb);
}

__device__ __forceinline__ uint32_t smem_u32(const void* p) {
    return (uint32_t)__cvta_generic_to_shared(p);
}

__device__ __forceinline__ void ldmx4(uint32_t& r0, uint32_t& r1, uint32_t& r2, uint32_t& r3,
                                      uint32_t addr) {
    asm volatile("ldmatrix.sync.aligned.m8n8.x4.shared.b16 {%0,%1,%2,%3}, [%4];"
                 : "=r"(r0), "=r"(r1), "=r"(r2), "=r"(r3) : "r"(addr));
}
__device__ __forceinline__ void ldmx2(uint32_t& r0, uint32_t& r1, uint32_t addr) {
    asm volatile("ldmatrix.sync.aligned.m8n8.x2.shared.b16 {%0,%1}, [%2];"
                 : "=r"(r0), "=r"(r1) : "r"(addr));
}
__device__ __forceinline__ void mma_bf16(float* d, const uint32_t* a, const uint32_t* b) {
    asm volatile(
        "mma.sync.aligned.m16n8k16.row.col.f32.bf16.bf16.f32 "
        "{%0,%1,%2,%3}, {%4,%5,%6,%7}, {%8,%9}, {%0,%1,%2,%3};"
        : "+f"(d[0]), "+f"(d[1]), "+f"(d[2]), "+f"(d[3])
        : "r"(a[0]), "r"(a[1]), "r"(a[2]), "r"(a[3]), "r"(b[0]), "r"(b[1]));
}

// ---------------------------------------------------------------------------
// convert_init: split X and W_ih into bf16 hi/lo, build bias, zero sync.
// ---------------------------------------------------------------------------
__global__ void convert_init(const float* __restrict__ X, const float* __restrict__ W,
                             const float* __restrict__ b1, const float* __restrict__ b2)
{
    size_t i0 = (size_t)blockIdx.x * blockDim.x + threadIdx.x;
    size_t stride = (size_t)gridDim.x * blockDim.x;
    const size_t NX4 = (size_t)TT * BB * II / 4;
    const size_t NW4 = (size_t)G4 * II / 4;

    for (size_t i = i0; i < NX4; i += stride) {
        float4 v = ((const float4*)X)[i];
        uint32_t h0, h1, h2, h3, l0, l1, l2, l3;
        split2(v.x, h0, l0); split2(v.y, h1, l1);
        split2(v.z, h2, l2); split2(v.w, h3, l3);
        ((uint2*)g_Xhi)[i] = make_uint2(h0 | (h1 << 16), h2 | (h3 << 16));
        ((uint2*)g_Xlo)[i] = make_uint2(l0 | (l1 << 16), l2 | (l3 << 16));
    }
    for (size_t i = i0; i < NW4; i += stride) {
        float4 v = ((const float4*)W)[i];
        uint32_t h0, h1, h2, h3, l0, l1, l2, l3;
        split2(v.x, h0, l0); split2(v.y, h1, l1);
        split2(v.z, h2, l2); split2(v.w, h3, l3);
        ((uint2*)g_Whi)[i] = make_uint2(h0 | (h1 << 16), h2 | (h3 << 16));
        ((uint2*)g_Wlo)[i] = make_uint2(l0 | (l1 << 16), l2 | (l3 << 16));
    }
    for (size_t i = i0; i < G4; i += stride) g_bias[i] = b1[i] + b2[i];
    if (i0 == 0) g_sync = 0u;
}

// ---------------------------------------------------------------------------
// sgemm_bf16: g_xg[m][n] = sum_k X[m][k] * W_ih[n][k] + bias[n]
// M=65536, N=2048, K=512, split-bf16 3-pass mma. 128x128x32 tiles, 8 warps,
// warp tile m32 x n64. Register prefetch pipelines the global loads.
// ---------------------------------------------------------------------------
__global__ void __launch_bounds__(256) sgemm_bf16()
{
    __shared__ __nv_bfloat16 Ah[128 * 40], Al[128 * 40], Bh[128 * 40], Bl[128 * 40];

    const int t    = threadIdx.x;
    const int lane = t & 31;
    const int w    = t >> 5;
    const int wm   = w >> 1;          // 0..3
    const int wn   = w & 1;           // 0..1
    const int m0   = blockIdx.y * 128;
    const int n0   = blockIdx.x * 128;

    // tile-load mapping: pair p = t + 256*i -> row = p>>2 (+64 for i=1), grp = p&3
    const int row0 = t >> 2;
    const int grp  = t & 3;
    size_t ao0 = (size_t)(m0 + row0) * II + grp * 8;
    size_t ao1 = ao0 + (size_t)64 * II;
    size_t bo0 = (size_t)(n0 + row0) * II + grp * 8;
    size_t bo1 = bo0 + (size_t)64 * II;
    const int s0 = row0 * 40 + grp * 8;
    const int s1 = s0 + 64 * 40;

    const uint32_t uAh = smem_u32(Ah), uAl = smem_u32(Al);
    const uint32_t uBh = smem_u32(Bh), uBl = smem_u32(Bl);
    const int a_r = lane & 15, a_c = (lane >> 4) << 3;
    const int b_r = lane & 7,  b_c = ((lane >> 3) & 1) << 3;

    float d[2][8][4] = {{{0.f}}};

    uint4 pAh0 = *(const uint4*)(g_Xhi + ao0);
    uint4 pAh1 = *(const uint4*)(g_Xhi + ao1);
    uint4 pAl0 = *(const uint4*)(g_Xlo + ao0);
    uint4 pAl1 = *(const uint4*)(g_Xlo + ao1);
    uint4 pBh0 = *(const uint4*)(g_Whi + bo0);
    uint4 pBh1 = *(const uint4*)(g_Whi + bo1);
    uint4 pBl0 = *(const uint4*)(g_Wlo + bo0);
    uint4 pBl1 = *(const uint4*)(g_Wlo + bo1);

    for (int it = 0; it < 16; ++it) {
        __syncthreads();
        *(uint4*)(Ah + s0) = pAh0; *(uint4*)(Ah + s1) = pAh1;
        *(uint4*)(Al + s0) = pAl0; *(uint4*)(Al + s1) = pAl1;
        *(uint4*)(Bh + s0) = pBh0; *(uint4*)(Bh + s1) = pBh1;
        *(uint4*)(Bl + s0) = pBl0; *(uint4*)(Bl + s1) = pBl1;
        __syncthreads();

        if (it != 15) {
            ao0 += 32; ao1 += 32; bo0 += 32; bo1 += 32;
            pAh0 = *(const uint4*)(g_Xhi + ao0);
            pAh1 = *(const uint4*)(g_Xhi + ao1);
            pAl0 = *(const uint4*)(g_Xlo + ao0);
            pAl1 = *(const uint4*)(g_Xlo + ao1);
            pBh0 = *(const uint4*)(g_Whi + bo0);
            pBh1 = *(const uint4*)(g_Whi + bo1);
            pBl0 = *(const uint4*)(g_Wlo + bo0);
            pBl1 = *(const uint4*)(g_Wlo + bo1);
        }

#pragma unroll
        for (int ks = 0; ks < 2; ++ks) {
            uint32_t ah[2][4], al[2][4];
#pragma unroll
            for (int mt = 0; mt < 2; ++mt) {
                uint32_t ra = uAh + (uint32_t)(((wm * 32 + mt * 16 + a_r) * 40 + ks * 16 + a_c) * 2);
                ldmx4(ah[mt][0], ah[mt][1], ah[mt][2], ah[mt][3], ra);
                uint32_t rl = uAl + (uint32_t)(((wm * 32 + mt * 16 + a_r) * 40 + ks * 16 + a_c) * 2);
                ldmx4(al[mt][0], al[mt][1], al[mt][2], al[mt][3], rl);
            }
#pragma unroll
            for (int nt = 0; nt < 8; ++nt) {
                uint32_t bh[2], bl[2];
                uint32_t rb = uBh + (uint32_t)(((wn * 64 + nt * 8 + b_r) * 40 + ks * 16 + b_c) * 2);
                ldmx2(bh[0], bh[1], rb);
                uint32_t rlb = uBl + (uint32_t)(((wn * 64 + nt * 8 + b_r) * 40 + ks * 16 + b_c) * 2);
                ldmx2(bl[0], bl[1], rlb);
#pragma unroll
                for (int mt = 0; mt < 2; ++mt) {
                    mma_bf16(d[mt][nt], ah[mt], bh);
                    mma_bf16(d[mt][nt], ah[mt], bl);
                    mma_bf16(d[mt][nt], al[mt], bh);
                }
            }
        }
    }

    // epilogue: add bias, write fp32
    const int gid = lane >> 2, tig = lane & 3;
#pragma unroll
    for (int mt = 0; mt < 2; ++mt) {
#pragma unroll
        for (int nt = 0; nt < 8; ++nt) {
            int col = n0 + wn * 64 + nt * 8 + 2 * tig;
            float bb0 = g_bias[col], bb1 = g_bias[col + 1];
            int r = m0 + wm * 32 + mt * 16 + gid;
            float2 v0 = make_float2(d[mt][nt][0] + bb0, d[mt][nt][1] + bb1);
            float2 v1 = make_float2(d[mt][nt][2] + bb0, d[mt][nt][3] + bb1);
            *(float2*)&g_xg[(size_t)r * G4 + col]       = v0;
            *(float2*)&g_xg[(size_t)(r + 8) * G4 + col] = v1;
        }
    }
}

// ---------------------------------------------------------------------------
// Persistent recurrent kernel (tensor-core). 128 blocks x 256 threads.
// Block g owns h-cols [4g,4g+4) -> 16 gate cols j=q*4+ci (row n=q*512+hc0+ci).
// Per step: C[128x16] = h_{t-1} @ Ws^T via split-bf16 mma; warp w owns rows
// 16w..16w+15 (no cross-warp reduction). Fused fp32 LSTM elementwise; c in regs.
// ---------------------------------------------------------------------------
__global__ void __launch_bounds__(256, 1) lstm_rec(const float* __restrict__ Whh,
                                                   float* __restrict__ out,
                                                   int tail)
{
    __shared__ __nv_bfloat16 Wsh[16 * 520];
    __shared__ __nv_bfloat16 Wsl[16 * 520];
    __shared__ float Cs[128 * 18];

    const int tid  = threadIdx.x;
    const int lane = tid & 31;
    const int w    = tid >> 5;
    const int gid  = lane >> 2;
    const int tig  = lane & 3;
    const int hc0  = blockIdx.x * 4;

    // Load + split W_hh slice: Ws[j][k] = Whh[q*512+hc0+ci][k], j=q*4+ci
    for (int idx = tid; idx < 16 * 512; idx += 256) {
        int j = idx >> 9, k = idx & 511;
        int n = (j >> 2) * 512 + hc0 + (j & 3);
        float v = Whh[(size_t)n * HH + k];
        uint32_t hb, lb;
        split2(v, hb, lb);
        Wsh[j * 520 + k] = __ushort_as_bfloat16((unsigned short)hb);
        Wsl[j * 520 + k] = __ushort_as_bfloat16((unsigned short)lb);
    }
    __syncthreads();

    const int arow = 16 * w + gid;     // mma A row for this thread (a0/a2)
    float creg[2] = {0.f, 0.f};        // cell state for this thread's 2 (b,ci) pairs

    for (int t = 0; t < TT; ++t) {
        if (t > 0) {
            const uint32_t* hp = g_hpk[(t - 1) & 1];
            float d[2][4] = {{0.f, 0.f, 0.f, 0.f}};

#pragma unroll 4
            for (int kk = 0; kk < 32; ++kk) {
                const int kb = kk * 16;
                uint2 v00 = *(const uint2*)(hp + (size_t)arow * 512 + kb + 2 * tig);
                uint2 v01 = *(const uint2*)(hp + (size_t)arow * 512 + kb + 8 + 2 * tig);
                uint2 v10 = *(const uint2*)(hp + (size_t)(arow + 8) * 512 + kb + 2 * tig);
                uint2 v11 = *(const uint2*)(hp + (size_t)(arow + 8) * 512 + kb + 8 + 2 * tig);
                uint32_t ah[4], al[4];
                ah[0] = __byte_perm(v00.x, v00.y, 0x5410);
                ah[1] = __byte_perm(v10.x, v10.y, 0x5410);
                ah[2] = __byte_perm(v01.x, v01.y, 0x5410);
                ah[3] = __byte_perm(v11.x, v11.y, 0x5410);
                al[0] = __byte_perm(v00.x, v00.y, 0x7632);
                al[1] = __byte_perm(v10.x, v10.y, 0x7632);
                al[2] = __byte_perm(v01.x, v01.y, 0x7632);
                al[3] = __byte_perm(v11.x, v11.y, 0x7632);

#pragma unroll
                for (int nt = 0; nt < 2; ++nt) {
                    uint32_t bh[2], bl[2];
                    const int brow = (nt * 8 + gid) * 520;
                    bh[0] = *(const uint32_t*)&Wsh[brow + kb + 2 * tig];
                    bh[1] = *(const uint32_t*)&Wsh[brow + kb + 8 + 2 * tig];
                    bl[0] = *(const uint32_t*)&Wsl[brow + kb + 2 * tig];
                    bl[1] = *(const uint32_t*)&Wsl[brow + kb + 8 + 2 * tig];
                    mma_bf16(d[nt], ah, bh);
                    mma_bf16(d[nt], ah, bl);
                    mma_bf16(d[nt], al, bh);
                }
            }

            // dump C fragments to smem
#pragma unroll
            for (int nt = 0; nt < 2; ++nt) {
                *(float2*)&Cs[arow * 18 + nt * 8 + 2 * tig]       = make_float2(d[nt][0], d[nt][1]);
                *(float2*)&Cs[(arow + 8) * 18 + nt * 8 + 2 * tig] = make_float2(d[nt][2], d[nt][3]);
            }
        }
        __syncthreads();

        // Fused fp32 LSTM elementwise: 512 (b,ci) pairs, 2 per thread.
        const float* xgt = g_xg + (size_t)t * BB * G4;
        uint32_t* hw = g_hpk[t & 1];
#pragma unroll
        for (int pi = 0; pi < 2; ++pi) {
            int p  = tid + pi * 256;
            int ci = p >> 7;
            int b  = p & 127;
            float gate[4];
#pragma unroll
            for (int q = 0; q < 4; ++q) {
                float s = (t > 0) ? Cs[b * 18 + q * 4 + ci] : 0.f;
                gate[q] = s + xgt[(size_t)b * G4 + q * 512 + hc0 + ci];
            }
            float ig = 1.0f / (1.0f + __expf(-gate[0]));
            float fg = 1.0f / (1.0f + __expf(-gate[1]));
            float gg = tanhf(gate[2]);
            float og = 1.0f / (1.0f + __expf(-gate[3]));
            float cn = fg * creg[pi] + ig * gg;
            creg[pi] = cn;
            float h = og * tanhf(cn);
            int idx = b * HH + hc0 + ci;
            out[(size_t)t * BB * HH + idx] = h;
            uint32_t hb, lb;
            split2(h, hb, lb);
            hw[idx] = hb | (lb << 16);
        }

        // grid barrier between steps
        __syncthreads();
        if (tid == 0) {
            __threadfence();
            atomicAdd(&g_sync, 1u);
            unsigned target = (unsigned)(t + 1) * NBLK;
            while (*(volatile unsigned*)&g_sync < target) { }
            __threadfence();
        }
        __syncthreads();
    }

    // tail: hT copy + cT from registers
    if (tail) {
#pragma unroll
        for (int pi = 0; pi < 2; ++pi) {
            int p  = tid + pi * 256;
            int ci = p >> 7;
            int b  = p & 127;
            int idx = b * HH + hc0 + ci;
            out[TBH + idx]           = out[(size_t)(TT - 1) * BB * HH + idx];
            out[TBH + BB * HH + idx] = creg[pi];
        }
    }
}

// ---------------------------------------------------------------------------
extern "C" void kernel_launch(void* const* d_in, const int* in_sizes, int n_in,
                              void* d_out, int out_size)
{
    const float* input = (const float*)d_in[0];
    /* d_in[1] = time, unused by the base cell */
    const float* W_ih  = (const float*)d_in[2];
    const float* W_hh  = (const float*)d_in[3];
    const float* b_ih  = (const float*)d_in[4];
    const float* b_hh  = (const float*)d_in[5];
    float* out = (float*)d_out;

    int tail = ((size_t)out_size >= TBH + 2ull * BB * HH) ? 1 : 0;

    convert_init<<<2048, 256>>>(input, W_ih, b_ih, b_hh);
    sgemm_bf16<<<dim3(16, 512), 256>>>();
    lstm_rec<<<NBLK, 256>>>(W_hh, out, tail);
}